// round 9
// baseline (speedup 1.0000x reference)
#include <cuda_runtime.h>
#include <cstdint>

// Problem constants (fixed-shape variant)
#define BS 4
#define NQ 10000
#define NH 8
#define HD 32
#define NP 4
#define SH 100
#define SW 100

// value layout: [b][pix][h][d], pix = y*SW + x  (pixel stride = 256 floats = 64 float4)
// loc: [b][q][h][0][p][2]   aw: [b][q][h][0][p]   out: [b][q][h*HD+d]
//
// One warp = (b, q, head-group hg) covering heads hg*4..hg*4+3.
// Consume mapping: g = lane>>3 (head in group), sub = lane&7 (float4 slot, 32 ch).
// Scalar bilinear math for the 16 (head,point) combos is computed ONCE by
// lanes 0..15 (lane c -> head gc=c>>2, point pc=c&3) and broadcast via shfl.

__global__ __launch_bounds__(256) void deform_attn_kernel_v3(
    const float* __restrict__ value,
    const float* __restrict__ loc,
    const float* __restrict__ aw,
    float* __restrict__ out)
{
    const int gtid = blockIdx.x * blockDim.x + threadIdx.x;
    const int warp = gtid >> 5;
    const int lane = gtid & 31;
    if (warp >= BS * NQ * (NH / 4)) return;

    const int hg = warp & 1;
    const int bq = warp >> 1;           // b*NQ + q
    const int b  = bq / NQ;

    // ---- compute phase: lane c (all lanes run it on c = lane&15; duplicates harmless)
    const int c  = lane & 15;           // combo: head gc = c>>2, point pc = c&3
    const int idx = bq * (NH * NP) + (hg << 4) + c;   // (bq*8 + head)*4 + pc

    const float2 l = __ldg(reinterpret_cast<const float2*>(loc) + idx);
    const float  w = __ldg(aw + idx);

    const float x = fmaf(l.x, (float)SW, -0.5f);
    const float y = fmaf(l.y, (float)SH, -0.5f);
    const int x0 = __float2int_rd(x);
    const int y0 = __float2int_rd(y);
    const float tx = x - (float)x0;
    const float ty = y - (float)y0;

    // weights factored: 6 mul/fma
    float wy1 = ty * w;
    float wy0 = w - wy1;
    float w00 = fmaf(-tx, wy0, wy0);
    float w10 = tx * wy0;
    float w01 = fmaf(-tx, wy1, wy1);
    float w11 = tx * wy1;

    // validity via unsigned compare; zero the weight, clamp offset to 0 (safe addr)
    const bool vx0 = (unsigned)x0 < (unsigned)SW;
    const bool vx1 = (unsigned)(x0 + 1) < (unsigned)SW;
    const bool vy0 = (unsigned)y0 < (unsigned)SH;
    const bool vy1 = (unsigned)(y0 + 1) < (unsigned)SH;

    if (!vx0) { w00 = 0.f; w01 = 0.f; }
    if (!vx1) { w10 = 0.f; w11 = 0.f; }
    if (!vy0) { w00 = 0.f; w10 = 0.f; }
    if (!vy1) { w01 = 0.f; w11 = 0.f; }

    const int xs0 = vx0 ? x0 : 0;
    const int xs1 = vx1 ? (x0 + 1) : 0;
    const int ys0 = vy0 ? y0 : 0;
    const int ys1 = vy1 ? (y0 + 1) : 0;

    // float4-unit offsets: pix*64 + head*8 (head = hg*4 + gc)
    const int hterm = ((hg << 2) + (c >> 2)) << 3;
    const int ra = ys0 * (SW * 64) + hterm;
    const int rb = ys1 * (SW * 64) + hterm;
    const int ca = xs0 << 6;
    const int cb = xs1 << 6;
    const int o00 = ra + ca;
    const int o10 = ra + cb;
    const int o01 = rb + ca;
    const int o11 = rb + cb;

    // ---- consume phase
    const int sub = lane & 7;
    const float4* __restrict__ vb =
        reinterpret_cast<const float4*>(value) +
        (size_t)b * (SH * SW * (NH * HD / 4)) + sub;

    const int srcbase = (lane >> 3) << 2;   // combos for my head: srcbase + p

    float4 accA = make_float4(0.f, 0.f, 0.f, 0.f);
    float4 accB = make_float4(0.f, 0.f, 0.f, 0.f);

#pragma unroll
    for (int p = 0; p < NP; ++p) {
        const int s = srcbase + p;
        const float W00 = __shfl_sync(0xffffffffu, w00, s);
        const float W10 = __shfl_sync(0xffffffffu, w10, s);
        const float W01 = __shfl_sync(0xffffffffu, w01, s);
        const float W11 = __shfl_sync(0xffffffffu, w11, s);
        const int   O00 = __shfl_sync(0xffffffffu, o00, s);
        const int   O10 = __shfl_sync(0xffffffffu, o10, s);
        const int   O01 = __shfl_sync(0xffffffffu, o01, s);
        const int   O11 = __shfl_sync(0xffffffffu, o11, s);

        const float4 v00 = __ldg(vb + O00);
        const float4 v10 = __ldg(vb + O10);
        const float4 v01 = __ldg(vb + O01);
        const float4 v11 = __ldg(vb + O11);

        accA.x = fmaf(W00, v00.x, accA.x); accA.y = fmaf(W00, v00.y, accA.y);
        accA.z = fmaf(W00, v00.z, accA.z); accA.w = fmaf(W00, v00.w, accA.w);
        accB.x = fmaf(W10, v10.x, accB.x); accB.y = fmaf(W10, v10.y, accB.y);
        accB.z = fmaf(W10, v10.z, accB.z); accB.w = fmaf(W10, v10.w, accB.w);
        accA.x = fmaf(W01, v01.x, accA.x); accA.y = fmaf(W01, v01.y, accA.y);
        accA.z = fmaf(W01, v01.z, accA.z); accA.w = fmaf(W01, v01.w, accA.w);
        accB.x = fmaf(W11, v11.x, accB.x); accB.y = fmaf(W11, v11.y, accB.y);
        accB.z = fmaf(W11, v11.z, accB.z); accB.w = fmaf(W11, v11.w, accB.w);
    }

    float4 acc;
    acc.x = accA.x + accB.x;
    acc.y = accA.y + accB.y;
    acc.z = accA.z + accB.z;
    acc.w = accA.w + accB.w;

    // out float4 index: bq*64 + head*8 + sub = bq*64 + hg*32 + lane (contiguous per warp)
    reinterpret_cast<float4*>(out)[(size_t)bq * (NH * HD / 4) + (hg << 5) + lane] = acc;
}

extern "C" void kernel_launch(void* const* d_in, const int* in_sizes, int n_in,
                              void* d_out, int out_size)
{
    const float* value = (const float*)d_in[0];
    // d_in[1] = value_spatial_shapes (int64), unused
    const float* loc = (const float*)d_in[2];
    const float* aw = (const float*)d_in[3];
    float* out = (float*)d_out;

    const int total_warps = BS * NQ * (NH / 4);      // 80000
    const int threads = 256;
    const int blocks = (total_warps * 32 + threads - 1) / threads;  // 10000

    deform_attn_kernel_v3<<<blocks, threads>>>(value, loc, aw, out);
}